// round 15
// baseline (speedup 1.0000x reference)
#include <cuda_runtime.h>
#include <cuda_fp16.h>
#include <cstdint>

// Problem constants
#define BATCH 4
#define SEQ   2048
#define DMODEL 2048
#define NHEAD 16
#define HDIM  128
#define MROWS (BATCH * SEQ)   // 8192

// ---------------------------------------------------------------------------
// Scratch (device globals; allocation in kernel_launch is forbidden)
// ---------------------------------------------------------------------------
__device__ __half g_Xq[(size_t)MROWS * DMODEL];
__device__ __half g_Xk[(size_t)MROWS * DMODEL];
__device__ __half g_Xv[(size_t)MROWS * DMODEL];
__device__ __half g_Wq[(size_t)DMODEL * DMODEL];
__device__ __half g_Wk[(size_t)DMODEL * DMODEL];
__device__ __half g_Wv[(size_t)DMODEL * DMODEL];
__device__ __half g_Wo[(size_t)DMODEL * DMODEL];
__device__ __half g_Qh[(size_t)MROWS * DMODEL];
__device__ __half g_Kh[(size_t)MROWS * DMODEL];
__device__ __half g_Vh[(size_t)MROWS * DMODEL];
__device__ __half g_Ch[(size_t)MROWS * DMODEL];

// ---------------------------------------------------------------------------
// PTX helpers (sm_80-level: mma.sync / ldmatrix / cp.async)
// ---------------------------------------------------------------------------
__device__ __forceinline__ uint32_t smem_u32(const void* p) {
    uint32_t a;
    asm("{ .reg .u64 t; cvta.to.shared.u64 t, %1; cvt.u32.u64 %0, t; }"
        : "=r"(a) : "l"(p));
    return a;
}
__device__ __forceinline__ void ldsm4(uint32_t* r, uint32_t addr) {
    asm volatile("ldmatrix.sync.aligned.m8n8.x4.shared.b16 {%0,%1,%2,%3}, [%4];"
                 : "=r"(r[0]), "=r"(r[1]), "=r"(r[2]), "=r"(r[3]) : "r"(addr));
}
__device__ __forceinline__ void ldsm4t(uint32_t* r, uint32_t addr) {
    asm volatile("ldmatrix.sync.aligned.m8n8.x4.trans.shared.b16 {%0,%1,%2,%3}, [%4];"
                 : "=r"(r[0]), "=r"(r[1]), "=r"(r[2]), "=r"(r[3]) : "r"(addr));
}
__device__ __forceinline__ void mma_f16(float* d, const uint32_t* a,
                                        const uint32_t* b) {
    asm volatile(
        "mma.sync.aligned.m16n8k16.row.col.f32.f16.f16.f32 "
        "{%0,%1,%2,%3}, {%4,%5,%6,%7}, {%8,%9}, {%0,%1,%2,%3};"
        : "+f"(d[0]), "+f"(d[1]), "+f"(d[2]), "+f"(d[3])
        : "r"(a[0]), "r"(a[1]), "r"(a[2]), "r"(a[3]), "r"(b[0]), "r"(b[1]));
}
// Mixed cache policy: .ca (L1 fill) for cross-CTA-shared operands,
// .cg (L1 bypass) for CTA-private operands.
__device__ __forceinline__ void cp16_ca(uint32_t dst, const void* src) {
    asm volatile("cp.async.ca.shared.global [%0], [%1], 16;"
                 :: "r"(dst), "l"(src) : "memory");
}
__device__ __forceinline__ void cp16_cg(uint32_t dst, const void* src) {
    asm volatile("cp.async.cg.shared.global [%0], [%1], 16;"
                 :: "r"(dst), "l"(src) : "memory");
}
#define CP_COMMIT asm volatile("cp.async.commit_group;" ::: "memory")
#define CP_WAIT0  asm volatile("cp.async.wait_group 0;" ::: "memory")

// pack two fp32 -> half2 (first arg -> low half)
__device__ __forceinline__ uint32_t pack_h2(float lo, float hi) {
    uint32_t r;
    asm("cvt.rn.f16x2.f32 %0, %1, %2;" : "=r"(r) : "f"(hi), "f"(lo));
    return r;
}
// raw exp2 (MUFU.EX2) — softmax runs in log2 domain
__device__ __forceinline__ float ex2f(float x) {
    float r;
    asm("ex2.approx.f32 %0, %1;" : "=f"(r) : "f"(x));
    return r;
}

// 1/sqrt(128) * log2(e): folded into Q so QK^T scores are log2-domain.
#define QSCALE (0.08838834764831843f * 1.4426950408889634f)

// ---------------------------------------------------------------------------
// Fused converts (fp32 -> fp16): q,k,v,Wq,Wk,Wv,Wo in ONE launch
// ---------------------------------------------------------------------------
#define NA4 (MROWS * DMODEL / 4)     // 4194304
#define NW4 (DMODEL * DMODEL / 4)    // 1048576

__global__ void __launch_bounds__(256) cvt7_f16(
    const float* __restrict__ x0, const float* __restrict__ x1,
    const float* __restrict__ x2,
    const float* __restrict__ w0, const float* __restrict__ w1,
    const float* __restrict__ w2, const float* __restrict__ w3,
    __half* __restrict__ a0, __half* __restrict__ a1, __half* __restrict__ a2,
    __half* __restrict__ b0, __half* __restrict__ b1,
    __half* __restrict__ b2, __half* __restrict__ b3)
{
    int i = blockIdx.x * 256 + threadIdx.x;
    const float* x;
    __half* h;
    int j;
    if (i < 3 * NA4) {
        int which = i / NA4;
        j = i - which * NA4;
        x = (which == 0) ? x0 : (which == 1) ? x1 : x2;
        h = (which == 0) ? a0 : (which == 1) ? a1 : a2;
    } else {
        int k = i - 3 * NA4;
        int which = k / NW4;
        j = k - which * NW4;
        x = (which == 0) ? w0 : (which == 1) ? w1 : (which == 2) ? w2 : w3;
        h = (which == 0) ? b0 : (which == 1) ? b1 : (which == 2) ? b2 : b3;
    }
    float4 v = ((const float4*)x)[j];
    ((uint2*)h)[j] = make_uint2(pack_h2(v.x, v.y), pack_h2(v.z, v.w));
}

// ---------------------------------------------------------------------------
// fp16 single-term GEMM:  C = A @ W^T
// CTA 128x128, BK=64, 8 warps (2x4, warp 64x32), 2-stage cp.async double
// buffer, 2 CTAs/SM. Rows padded to 144 B. Fragment loads hoisted per k16.
// A tile: .ca (shared with co-resident CTA, n-inner raster).
// W tile: .cg (private -> skip L1 fill, don't evict shared A lines).
// ---------------------------------------------------------------------------
#define G5_ROWB  144
#define G5_TILE  (128 * G5_ROWB)     // 18432
#define G5_STAGE (2 * G5_TILE)       // 36864 (A, W)
#define G5_SMEM  (2 * G5_STAGE)      // 73728 -> 2 CTAs/SM

__device__ __forceinline__ void g5_load(
    uint32_t smb, int stage, const __half* __restrict__ A,
    const __half* __restrict__ W, int m0, int n0, int k0, int tid)
{
    const __half* Ap = A + (size_t)m0 * DMODEL + k0;
    const __half* Wp = W + (size_t)n0 * DMODEL + k0;
    #pragma unroll
    for (int i = 0; i < 4; i++) {
        int v = i * 256 + tid;          // 0..1023 16B chunks
        int r = v >> 3;                 // 0..127
        int c = (v & 7) * 16;           // 0..112
        cp16_ca(smb + stage * G5_STAGE + r * G5_ROWB + c,
                (const char*)Ap + (size_t)r * DMODEL * 2 + c);
    }
    #pragma unroll
    for (int i = 0; i < 4; i++) {
        int v = i * 256 + tid;
        int r = v >> 3;
        int c = (v & 7) * 16;
        cp16_cg(smb + stage * G5_STAGE + G5_TILE + r * G5_ROWB + c,
                (const char*)Wp + (size_t)r * DMODEL * 2 + c);
    }
}

__device__ __forceinline__ void g5_mainloop(
    uint32_t smb, const __half* __restrict__ A, const __half* __restrict__ W,
    int m0, int n0, int tid, float acc[4][4][4])
{
    const int lane = tid & 31;
    const int wid  = tid >> 5;
    const int wm = wid >> 2;
    const int wn = wid & 3;
    const int a_row = wm * 64 + (lane & 15);
    const int a_cb  = ((lane >> 4) & 1) * 16;
    const int b_row = wn * 32 + (lane & 7) + ((lane >> 4) << 3);
    const int b_cb  = ((lane >> 3) & 1) * 16;

    const int nchunks = DMODEL / 64;   // 32
    g5_load(smb, 0, A, W, m0, n0, 0, tid);
    CP_COMMIT;

    for (int c = 0; c < nchunks; c++) {
        CP_WAIT0;
        __syncthreads();
        if (c + 1 < nchunks) {
            g5_load(smb, (c + 1) & 1, A, W, m0, n0, (c + 1) * 64, tid);
            CP_COMMIT;
        }

        const uint32_t st = smb + (c & 1) * G5_STAGE;
        #pragma unroll
        for (int kk = 0; kk < 4; kk++) {
            const int kb = kk * 32;
            uint32_t bh[4][2];
            #pragma unroll
            for (int nt2 = 0; nt2 < 2; nt2++) {
                uint32_t r4[4];
                ldsm4(r4, st + G5_TILE +
                          (b_row + nt2 * 16) * G5_ROWB + kb + b_cb);
                bh[nt2 * 2][0] = r4[0]; bh[nt2 * 2][1] = r4[1];
                bh[nt2 * 2 + 1][0] = r4[2]; bh[nt2 * 2 + 1][1] = r4[3];
            }
            uint32_t ah[4][4];
            #pragma unroll
            for (int mt = 0; mt < 4; mt++)
                ldsm4(ah[mt], st + (a_row + mt * 16) * G5_ROWB + kb + a_cb);
            #pragma unroll
            for (int mt = 0; mt < 4; mt++)
                #pragma unroll
                for (int nt = 0; nt < 4; nt++)
                    mma_f16(acc[mt][nt], ah[mt], bh[nt]);
        }
    }
}

// Fused Q/K/V projection GEMM: 3072 tiles. Q gets QSCALE (incl log2e) folded.
__global__ void __launch_bounds__(256, 2) gemm_qkv(
    const __half* __restrict__ xq, const __half* __restrict__ xk,
    const __half* __restrict__ xv,
    const __half* __restrict__ wq, const __half* __restrict__ wk,
    const __half* __restrict__ wv,
    __half* __restrict__ qh, __half* __restrict__ kh, __half* __restrict__ vh)
{
    extern __shared__ __align__(128) char sm[];
    const uint32_t smb = smem_u32(sm);
    const int t = blockIdx.x;
    const int which = t >> 10;
    const int idx = t & 1023;
    const int m0 = (idx >> 4) * 128;
    const int n0 = (idx & 15) * 128;
    const int tid = threadIdx.x;

    const __half* A = (which == 0) ? xq : (which == 1) ? xk : xv;
    const __half* W = (which == 0) ? wq : (which == 1) ? wk : wv;
    __half* Oh = (which == 0) ? qh : (which == 1) ? kh : vh;

    float acc[4][4][4];
    #pragma unroll
    for (int i = 0; i < 4; i++)
        #pragma unroll
        for (int j = 0; j < 4; j++)
            #pragma unroll
            for (int e = 0; e < 4; e++) acc[i][j][e] = 0.0f;

    g5_mainloop(smb, A, W, m0, n0, tid, acc);

    const int lane = tid & 31;
    const int wid  = tid >> 5;
    const float sc = (which == 0) ? QSCALE : 1.0f;
    #pragma unroll
    for (int mt = 0; mt < 4; mt++) {
        const int row = m0 + (wid >> 2) * 64 + mt * 16 + (lane >> 2);
        #pragma unroll
        for (int nt = 0; nt < 4; nt++) {
            const int col = n0 + (wid & 3) * 32 + nt * 8 + (lane & 3) * 2;
            *(uint32_t*)&Oh[(size_t)row * DMODEL + col] =
                pack_h2(acc[mt][nt][0] * sc, acc[mt][nt][1] * sc);
            *(uint32_t*)&Oh[(size_t)(row + 8) * DMODEL + col] =
                pack_h2(acc[mt][nt][2] * sc, acc[mt][nt][3] * sc);
        }
    }
}

// Output projection GEMM: fp32 result to d_out.
__global__ void __launch_bounds__(256, 2) gemm_out(
    const __half* __restrict__ A, const __half* __restrict__ W,
    float* __restrict__ C)
{
    extern __shared__ __align__(128) char sm[];
    const uint32_t smb = smem_u32(sm);
    const int m0 = blockIdx.y * 128;
    const int n0 = blockIdx.x * 128;
    const int tid = threadIdx.x;

    float acc[4][4][4];
    #pragma unroll
    for (int i = 0; i < 4; i++)
        #pragma unroll
        for (int j = 0; j < 4; j++)
            #pragma unroll
            for (int e = 0; e < 4; e++) acc[i][j][e] = 0.0f;

    g5_mainloop(smb, A, W, m0, n0, tid, acc);

    const int lane = tid & 31;
    const int wid  = tid >> 5;
    #pragma unroll
    for (int mt = 0; mt < 4; mt++) {
        const int row = m0 + (wid >> 2) * 64 + mt * 16 + (lane >> 2);
        #pragma unroll
        for (int nt = 0; nt < 4; nt++) {
            const int col = n0 + (wid & 3) * 32 + nt * 8 + (lane & 3) * 2;
            *(float2*)&C[(size_t)row * DMODEL + col] =
                make_float2(acc[mt][nt][0], acc[mt][nt][1]);
            *(float2*)&C[(size_t)(row + 8) * DMODEL + col] =
                make_float2(acc[mt][nt][2], acc[mt][nt][3]);
        }
    }
}

// ---------------------------------------------------------------------------
// Flash attention, fp16 HMMA, double-buffered KV, log2-domain softmax.
// BQ=64, BKV=64, 4 warps/CTA, 2 CTAs/SM. KV via .ca (shared with the
// co-resident adjacent-qt CTA); Q via .cg (private).
// ---------------------------------------------------------------------------
#define FB_ROWB 272
#define FSTG    (2 * 64 * FB_ROWB)          // 34816 per stage (K + V)
#define FB_Q    (2 * FSTG)                  // 69632
#define FB_MSK  (FB_Q + 64 * FB_ROWB)       // 87040 (two 256 B slots)
#define FB_SMEM (FB_MSK + 512)              // 87552 -> 2 CTAs/SM

__device__ __forceinline__ void fl_loadkv64(
    uint32_t smb, int stg, const __half* __restrict__ kh,
    const __half* __restrict__ vh, const int* __restrict__ amask,
    int b, int h, int kt, int tid)
{
    const uint32_t base = smb + stg * FSTG;
    const size_t krow0 = (size_t)b * SEQ + (size_t)kt * 64;
    #pragma unroll
    for (int i = 0; i < 8; i++) {
        int idx = i * 128 + tid;
        int r = idx >> 4;
        int c = (idx & 15) * 16;
        size_t go = ((krow0 + r) * DMODEL + h * HDIM) * 2 + c;
        cp16_ca(base + r * FB_ROWB + c, (const char*)kh + go);
        cp16_ca(base + 64 * FB_ROWB + r * FB_ROWB + c, (const char*)vh + go);
    }
    if (tid < 16)
        cp16_ca(smb + FB_MSK + stg * 256 + tid * 16,
                (const char*)(amask + b * SEQ + kt * 64) + tid * 16);
}

__global__ void __launch_bounds__(128, 2) flash_f16(
    const __half* __restrict__ qh, const __half* __restrict__ kh,
    const __half* __restrict__ vh, const int* __restrict__ amask,
    __half* __restrict__ chi)
{
    extern __shared__ __align__(128) char sm[];
    const uint32_t smb = smem_u32(sm);

    const int b  = blockIdx.z;
    const int h  = blockIdx.y;
    const int qt = (int)gridDim.x - 1 - (int)blockIdx.x;   // heavy tiles first
    const int tid = threadIdx.x;
    const int wid = tid >> 5;
    const int lane = tid & 31;

    const size_t qrow0 = (size_t)b * SEQ + (size_t)qt * 64;

    #pragma unroll
    for (int i = 0; i < 8; i++) {
        int idx = i * 128 + tid;
        int r = idx >> 4;
        int c = (idx & 15) * 16;
        size_t go = ((qrow0 + r) * DMODEL + h * HDIM) * 2 + c;
        cp16_cg(smb + FB_Q + r * FB_ROWB + c, (const char*)qh + go);
    }
    fl_loadkv64(smb, 0, kh, vh, amask, b, h, 0, tid);
    CP_COMMIT;

    float o[16][4];
    #pragma unroll
    for (int nt = 0; nt < 16; nt++)
        #pragma unroll
        for (int e = 0; e < 4; e++) o[nt][e] = 0.0f;
    float mA = -1e30f, mB = -1e30f, lA = 0.0f, lB = 0.0f;
    uint32_t qf[8][4];

    const int rA = lane >> 2;
    const int growA = qt * 64 + wid * 16 + rA;
    const int growB = growA + 8;
    const uint32_t qbase = smb + FB_Q + (wid * 16 + (lane & 15)) * FB_ROWB +
                           ((lane >> 4) & 1) * 16;
    const uint32_t krel = ((lane & 7) + ((lane >> 4) << 3)) * FB_ROWB +
                          ((lane >> 3) & 1) * 16;
    const uint32_t vrel = 64 * FB_ROWB +
                          ((lane & 7) + ((lane >> 3) & 1) * 8) * FB_ROWB +
                          (lane >> 4) * 16;

    for (int kt = 0; kt <= qt; kt++) {
        CP_WAIT0;            // stage kt&1 resident
        __syncthreads();     // all warps done with stage (kt+1)&1 (iter kt-1)
        if (kt == 0) {
            #pragma unroll
            for (int kk = 0; kk < 8; kk++) ldsm4(qf[kk], qbase + kk * 32);
        }
        if (kt < qt)
            fl_loadkv64(smb, (kt + 1) & 1, kh, vh, amask, b, h, kt + 1, tid);
        CP_COMMIT;           // prefetch in flight UNDER this tile's compute

        const int stg = kt & 1;
        const uint32_t kvb = smb + stg * FSTG;
        const int* Ms = (const int*)(sm + FB_MSK + stg * 256);

        // ---- S = Qs K^T  (log2-domain scores) ----
        float s[8][4];
        #pragma unroll
        for (int nt = 0; nt < 8; nt++)
            #pragma unroll
            for (int e = 0; e < 4; e++) s[nt][e] = 0.0f;

        #pragma unroll
        for (int kk = 0; kk < 8; kk++) {
            #pragma unroll
            for (int g = 0; g < 4; g++) {
                uint32_t kf[4];
                ldsm4(kf, kvb + krel + g * 16 * FB_ROWB + kk * 32);
                mma_f16(s[2 * g], qf[kk], kf);
                mma_f16(s[2 * g + 1], qf[kk], kf + 2);
            }
        }

        // ---- mask (warp-uniform fast path) + row max ----
        int mybit = (Ms[lane] != 0) & (Ms[lane + 32] != 0);
        bool allones = (__ballot_sync(0xffffffffu, mybit) == 0xffffffffu);
        float tmaxA = -1e30f, tmaxB = -1e30f;
        if (allones && (kt * 64 + 63 <= qt * 64 + wid * 16)) {
            #pragma unroll
            for (int nt = 0; nt < 8; nt++) {
                tmaxA = fmaxf(tmaxA, fmaxf(s[nt][0], s[nt][1]));
                tmaxB = fmaxf(tmaxB, fmaxf(s[nt][2], s[nt][3]));
            }
        } else {
            #pragma unroll
            for (int nt = 0; nt < 8; nt++) {
                int lc = nt * 8 + (lane & 3) * 2;
                int gc = kt * 64 + lc;
                int mk0 = Ms[lc], mk1 = Ms[lc + 1];
                float v0 = s[nt][0]; if (gc > growA || !mk0) v0 = -10000.0f;
                float v1 = s[nt][1]; if (gc + 1 > growA || !mk1) v1 = -10000.0f;
                float v2 = s[nt][2]; if (gc > growB || !mk0) v2 = -10000.0f;
                float v3 = s[nt][3]; if (gc + 1 > growB || !mk1) v3 = -10000.0f;
                s[nt][0] = v0; s[nt][1] = v1; s[nt][2] = v2; s[nt][3] = v3;
                tmaxA = fmaxf(tmaxA, fmaxf(v0, v1));
                tmaxB = fmaxf(tmaxB, fmaxf(v2, v3));
            }
        }
        tmaxA = fmaxf(tmaxA, __shfl_xor_sync(0xffffffffu, tmaxA, 1));
        tmaxA = fmaxf(tmaxA, __shfl_xor_sync(0xffffffffu, tmaxA, 2));
        tmaxB = fmaxf(tmaxB, __shfl_xor_sync(0xffffffffu, tmaxB, 1));
        tmaxB = fmaxf(tmaxB, __shfl_xor_sync(0xffffffffu, tmaxB, 2));

        float mAn = fmaxf(mA, tmaxA), mBn = fmaxf(mB, tmaxB);
        float aAl = ex2f(mA - mAn), aBl = ex2f(mB - mBn);

        // ---- P = exp2(S - m) -> fp16 fragments ----
        uint32_t phi[8][2];
        float sumA = 0.0f, sumB = 0.0f;
        #pragma unroll
        for (int nt = 0; nt < 8; nt++) {
            float p0 = ex2f(s[nt][0] - mAn), p1 = ex2f(s[nt][1] - mAn);
            float p2 = ex2f(s[nt][2] - mBn), p3 = ex2f(s[nt][3] - mBn);
            sumA += p0 + p1; sumB += p2 + p3;
            phi[nt][0] = pack_h2(p0, p1);
            phi[nt][1] = pack_h2(p2, p3);
        }
        sumA += __shfl_xor_sync(0xffffffffu, sumA, 1);
        sumA += __shfl_xor_sync(0xffffffffu, sumA, 2);
        sumB += __shfl_xor_sync(0xffffffffu, sumB, 1);
        sumB += __shfl_xor_sync(0xffffffffu, sumB, 2);
        lA = lA * aAl + sumA;
        lB = lB * aBl + sumB;
        mA = mAn; mB = mBn;

        // ---- O rescale (skip when no row max moved in this warp) ----
        if (__ballot_sync(0xffffffffu,
                          (aAl == 1.0f) && (aBl == 1.0f)) != 0xffffffffu) {
            #pragma unroll
            for (int nt = 0; nt < 16; nt++) {
                o[nt][0] *= aAl; o[nt][1] *= aAl;
                o[nt][2] *= aBl; o[nt][3] *= aBl;
            }
        }

        // ---- O += P V ----
        #pragma unroll
        for (int t = 0; t < 4; t++) {
            uint32_t ah[4] = {phi[2 * t][0], phi[2 * t][1],
                              phi[2 * t + 1][0], phi[2 * t + 1][1]};
            #pragma unroll
            for (int g = 0; g < 8; g++) {
                uint32_t vf[4];
                ldsm4t(vf, kvb + vrel + t * 16 * FB_ROWB + g * 32);
                mma_f16(o[2 * g], ah, vf);
                mma_f16(o[2 * g + 1], ah, vf + 2);
            }
        }
    }

    // ---- normalize + store context (fp16) ----
    const float invA = 1.0f / lA, invB = 1.0f / lB;
    const size_t rgA = qrow0 + wid * 16 + rA;
    const size_t rgB = rgA + 8;
    #pragma unroll
    for (int nt = 0; nt < 16; nt++) {
        int col = h * HDIM + nt * 8 + (lane & 3) * 2;
        *(uint32_t*)&chi[rgA * DMODEL + col] =
            pack_h2(o[nt][0] * invA, o[nt][1] * invA);
        *(uint32_t*)&chi[rgB * DMODEL + col] =
            pack_h2(o[nt][2] * invB, o[nt][3] * invB);
    }
}

// ---------------------------------------------------------------------------
// Launch: cvt7, gemm_qkv, flash, gemm_out  (4 launches)
// ---------------------------------------------------------------------------
extern "C" void kernel_launch(void* const* d_in, const int* in_sizes, int n_in,
                              void* d_out, int out_size)
{
    const float* query = (const float*)d_in[0];
    const float* key   = (const float*)d_in[1];
    const float* value = (const float*)d_in[2];
    const int*   amask = (const int*)  d_in[3];
    const float* Wq    = (const float*)d_in[4];
    const float* Wk    = (const float*)d_in[5];
    const float* Wv    = (const float*)d_in[6];
    const float* Wo    = (const float*)d_in[7];
    float* out = (float*)d_out;

    __half *xq, *xk, *xv, *wq, *wk, *wv, *wo, *qh, *kh, *vh, *ch;
    cudaGetSymbolAddress((void**)&xq, g_Xq);
    cudaGetSymbolAddress((void**)&xk, g_Xk);
    cudaGetSymbolAddress((void**)&xv, g_Xv);
    cudaGetSymbolAddress((void**)&wq, g_Wq);
    cudaGetSymbolAddress((void**)&wk, g_Wk);
    cudaGetSymbolAddress((void**)&wv, g_Wv);
    cudaGetSymbolAddress((void**)&wo, g_Wo);
    cudaGetSymbolAddress((void**)&qh, g_Qh);
    cudaGetSymbolAddress((void**)&kh, g_Kh);
    cudaGetSymbolAddress((void**)&vh, g_Vh);
    cudaGetSymbolAddress((void**)&ch, g_Ch);

    cudaFuncSetAttribute(gemm_qkv,
                         cudaFuncAttributeMaxDynamicSharedMemorySize, G5_SMEM);
    cudaFuncSetAttribute(gemm_out,
                         cudaFuncAttributeMaxDynamicSharedMemorySize, G5_SMEM);
    cudaFuncSetAttribute(flash_f16,
                         cudaFuncAttributeMaxDynamicSharedMemorySize, FB_SMEM);

    cvt7_f16<<<(3 * NA4 + 4 * NW4) / 256, 256>>>(
        query, key, value, Wq, Wk, Wv, Wo,
        xq, xk, xv, wq, wk, wv, wo);

    gemm_qkv<<<3072, 256, G5_SMEM>>>(xq, xk, xv, wq, wk, wv, qh, kh, vh);

    flash_f16<<<dim3(SEQ / 64, NHEAD, BATCH), 128, FB_SMEM>>>(
        qh, kh, vh, amask, ch);

    gemm_out<<<dim3(DMODEL / 128, MROWS / 128), 256, G5_SMEM>>>(ch, wo, out);
}

// round 16
// speedup vs baseline: 1.0314x; 1.0314x over previous
#include <cuda_runtime.h>
#include <cuda_fp16.h>
#include <cstdint>

// Problem constants
#define BATCH 4
#define SEQ   2048
#define DMODEL 2048
#define NHEAD 16
#define HDIM  128
#define MROWS (BATCH * SEQ)   // 8192

// ---------------------------------------------------------------------------
// Scratch (device globals; allocation in kernel_launch is forbidden)
// ---------------------------------------------------------------------------
__device__ __half g_Xq[(size_t)MROWS * DMODEL];
__device__ __half g_Xk[(size_t)MROWS * DMODEL];
__device__ __half g_Xv[(size_t)MROWS * DMODEL];
__device__ __half g_Wq[(size_t)DMODEL * DMODEL];
__device__ __half g_Wk[(size_t)DMODEL * DMODEL];
__device__ __half g_Wv[(size_t)DMODEL * DMODEL];
__device__ __half g_Wo[(size_t)DMODEL * DMODEL];
__device__ __half g_Qh[(size_t)MROWS * DMODEL];
__device__ __half g_Kh[(size_t)MROWS * DMODEL];
__device__ __half g_Vh[(size_t)MROWS * DMODEL];
__device__ __half g_Ch[(size_t)MROWS * DMODEL];

// ---------------------------------------------------------------------------
// PTX helpers (sm_80-level: mma.sync / ldmatrix / cp.async)
// ---------------------------------------------------------------------------
__device__ __forceinline__ uint32_t smem_u32(const void* p) {
    uint32_t a;
    asm("{ .reg .u64 t; cvta.to.shared.u64 t, %1; cvt.u32.u64 %0, t; }"
        : "=r"(a) : "l"(p));
    return a;
}
__device__ __forceinline__ void ldsm4(uint32_t* r, uint32_t addr) {
    asm volatile("ldmatrix.sync.aligned.m8n8.x4.shared.b16 {%0,%1,%2,%3}, [%4];"
                 : "=r"(r[0]), "=r"(r[1]), "=r"(r[2]), "=r"(r[3]) : "r"(addr));
}
__device__ __forceinline__ void ldsm4t(uint32_t* r, uint32_t addr) {
    asm volatile("ldmatrix.sync.aligned.m8n8.x4.trans.shared.b16 {%0,%1,%2,%3}, [%4];"
                 : "=r"(r[0]), "=r"(r[1]), "=r"(r[2]), "=r"(r[3]) : "r"(addr));
}
__device__ __forceinline__ void mma_f16(float* d, const uint32_t* a,
                                        const uint32_t* b) {
    asm volatile(
        "mma.sync.aligned.m16n8k16.row.col.f32.f16.f16.f32 "
        "{%0,%1,%2,%3}, {%4,%5,%6,%7}, {%8,%9}, {%0,%1,%2,%3};"
        : "+f"(d[0]), "+f"(d[1]), "+f"(d[2]), "+f"(d[3])
        : "r"(a[0]), "r"(a[1]), "r"(a[2]), "r"(a[3]), "r"(b[0]), "r"(b[1]));
}
// Uniform .ca (R14 proven best): co-resident CTAs share A / KV tiles via L1.
__device__ __forceinline__ void cp16(uint32_t dst, const void* src) {
    asm volatile("cp.async.ca.shared.global [%0], [%1], 16;"
                 :: "r"(dst), "l"(src) : "memory");
}
#define CP_COMMIT asm volatile("cp.async.commit_group;" ::: "memory")
#define CP_WAIT0  asm volatile("cp.async.wait_group 0;" ::: "memory")

// pack two fp32 -> half2 (first arg -> low half)
__device__ __forceinline__ uint32_t pack_h2(float lo, float hi) {
    uint32_t r;
    asm("cvt.rn.f16x2.f32 %0, %1, %2;" : "=r"(r) : "f"(hi), "f"(lo));
    return r;
}
// raw exp2 (MUFU.EX2) — softmax runs in log2 domain
__device__ __forceinline__ float ex2f(float x) {
    float r;
    asm("ex2.approx.f32 %0, %1;" : "=f"(r) : "f"(x));
    return r;
}

// 1/sqrt(128) * log2(e): folded into Q so QK^T scores are log2-domain.
#define QSCALE (0.08838834764831843f * 1.4426950408889634f)

// ---------------------------------------------------------------------------
// Fused converts (fp32 -> fp16): q,k,v,Wq,Wk,Wv,Wo in ONE launch
// ---------------------------------------------------------------------------
#define NA4 (MROWS * DMODEL / 4)     // 4194304
#define NW4 (DMODEL * DMODEL / 4)    // 1048576

__global__ void __launch_bounds__(256) cvt7_f16(
    const float* __restrict__ x0, const float* __restrict__ x1,
    const float* __restrict__ x2,
    const float* __restrict__ w0, const float* __restrict__ w1,
    const float* __restrict__ w2, const float* __restrict__ w3,
    __half* __restrict__ a0, __half* __restrict__ a1, __half* __restrict__ a2,
    __half* __restrict__ b0, __half* __restrict__ b1,
    __half* __restrict__ b2, __half* __restrict__ b3)
{
    int i = blockIdx.x * 256 + threadIdx.x;
    const float* x;
    __half* h;
    int j;
    if (i < 3 * NA4) {
        int which = i / NA4;
        j = i - which * NA4;
        x = (which == 0) ? x0 : (which == 1) ? x1 : x2;
        h = (which == 0) ? a0 : (which == 1) ? a1 : a2;
    } else {
        int k = i - 3 * NA4;
        int which = k / NW4;
        j = k - which * NW4;
        x = (which == 0) ? w0 : (which == 1) ? w1 : (which == 2) ? w2 : w3;
        h = (which == 0) ? b0 : (which == 1) ? b1 : (which == 2) ? b2 : b3;
    }
    float4 v = ((const float4*)x)[j];
    ((uint2*)h)[j] = make_uint2(pack_h2(v.x, v.y), pack_h2(v.z, v.w));
}

// ---------------------------------------------------------------------------
// fp16 single-term GEMM (R14 config):  C = A @ W^T
// CTA 128x128, BK=64, 8 warps (2x4, warp 64x32), 2-stage cp.async double
// buffer, 2 CTAs/SM. Rows padded to 144 B. Fragment loads hoisted per k16.
// ---------------------------------------------------------------------------
#define G5_ROWB  144
#define G5_TILE  (128 * G5_ROWB)     // 18432
#define G5_STAGE (2 * G5_TILE)       // 36864 (A, W)
#define G5_SMEM  (2 * G5_STAGE)      // 73728 -> 2 CTAs/SM

__device__ __forceinline__ void g5_load(
    uint32_t smb, int stage, const __half* __restrict__ A,
    const __half* __restrict__ W, int m0, int n0, int k0, int tid)
{
    const __half* srcs[2] = {A + (size_t)m0 * DMODEL + k0,
                             W + (size_t)n0 * DMODEL + k0};
    #pragma unroll
    for (int t = 0; t < 2; t++) {
        #pragma unroll
        for (int i = 0; i < 4; i++) {
            int v = i * 256 + tid;          // 0..1023 16B chunks
            int r = v >> 3;                 // 0..127
            int c = (v & 7) * 16;           // 0..112
            cp16(smb + stage * G5_STAGE + t * G5_TILE + r * G5_ROWB + c,
                 (const char*)srcs[t] + (size_t)r * DMODEL * 2 + c);
        }
    }
}

__device__ __forceinline__ void g5_mainloop(
    uint32_t smb, const __half* __restrict__ A, const __half* __restrict__ W,
    int m0, int n0, int tid, float acc[4][4][4])
{
    const int lane = tid & 31;
    const int wid  = tid >> 5;
    const int wm = wid >> 2;
    const int wn = wid & 3;
    const int a_row = wm * 64 + (lane & 15);
    const int a_cb  = ((lane >> 4) & 1) * 16;
    const int b_row = wn * 32 + (lane & 7) + ((lane >> 4) << 3);
    const int b_cb  = ((lane >> 3) & 1) * 16;

    const int nchunks = DMODEL / 64;   // 32
    g5_load(smb, 0, A, W, m0, n0, 0, tid);
    CP_COMMIT;

    for (int c = 0; c < nchunks; c++) {
        CP_WAIT0;
        __syncthreads();
        if (c + 1 < nchunks) {
            g5_load(smb, (c + 1) & 1, A, W, m0, n0, (c + 1) * 64, tid);
            CP_COMMIT;
        }

        const uint32_t st = smb + (c & 1) * G5_STAGE;
        #pragma unroll
        for (int kk = 0; kk < 4; kk++) {
            const int kb = kk * 32;
            uint32_t bh[4][2];
            #pragma unroll
            for (int nt2 = 0; nt2 < 2; nt2++) {
                uint32_t r4[4];
                ldsm4(r4, st + G5_TILE +
                          (b_row + nt2 * 16) * G5_ROWB + kb + b_cb);
                bh[nt2 * 2][0] = r4[0]; bh[nt2 * 2][1] = r4[1];
                bh[nt2 * 2 + 1][0] = r4[2]; bh[nt2 * 2 + 1][1] = r4[3];
            }
            uint32_t ah[4][4];
            #pragma unroll
            for (int mt = 0; mt < 4; mt++)
                ldsm4(ah[mt], st + (a_row + mt * 16) * G5_ROWB + kb + a_cb);
            #pragma unroll
            for (int mt = 0; mt < 4; mt++)
                #pragma unroll
                for (int nt = 0; nt < 4; nt++)
                    mma_f16(acc[mt][nt], ah[mt], bh[nt]);
        }
    }
}

// Fused Q/K/V projection GEMM: 3072 tiles. Q gets QSCALE (incl log2e) folded.
__global__ void __launch_bounds__(256, 2) gemm_qkv(
    const __half* __restrict__ xq, const __half* __restrict__ xk,
    const __half* __restrict__ xv,
    const __half* __restrict__ wq, const __half* __restrict__ wk,
    const __half* __restrict__ wv,
    __half* __restrict__ qh, __half* __restrict__ kh, __half* __restrict__ vh)
{
    extern __shared__ __align__(128) char sm[];
    const uint32_t smb = smem_u32(sm);
    const int t = blockIdx.x;
    const int which = t >> 10;
    const int idx = t & 1023;
    const int m0 = (idx >> 4) * 128;
    const int n0 = (idx & 15) * 128;
    const int tid = threadIdx.x;

    const __half* A = (which == 0) ? xq : (which == 1) ? xk : xv;
    const __half* W = (which == 0) ? wq : (which == 1) ? wk : wv;
    __half* Oh = (which == 0) ? qh : (which == 1) ? kh : vh;

    float acc[4][4][4];
    #pragma unroll
    for (int i = 0; i < 4; i++)
        #pragma unroll
        for (int j = 0; j < 4; j++)
            #pragma unroll
            for (int e = 0; e < 4; e++) acc[i][j][e] = 0.0f;

    g5_mainloop(smb, A, W, m0, n0, tid, acc);

    const int lane = tid & 31;
    const int wid  = tid >> 5;
    const float sc = (which == 0) ? QSCALE : 1.0f;
    #pragma unroll
    for (int mt = 0; mt < 4; mt++) {
        const int row = m0 + (wid >> 2) * 64 + mt * 16 + (lane >> 2);
        #pragma unroll
        for (int nt = 0; nt < 4; nt++) {
            const int col = n0 + (wid & 3) * 32 + nt * 8 + (lane & 3) * 2;
            *(uint32_t*)&Oh[(size_t)row * DMODEL + col] =
                pack_h2(acc[mt][nt][0] * sc, acc[mt][nt][1] * sc);
            *(uint32_t*)&Oh[(size_t)(row + 8) * DMODEL + col] =
                pack_h2(acc[mt][nt][2] * sc, acc[mt][nt][3] * sc);
        }
    }
}

// Output projection GEMM: fp32 result to d_out.
__global__ void __launch_bounds__(256, 2) gemm_out(
    const __half* __restrict__ A, const __half* __restrict__ W,
    float* __restrict__ C)
{
    extern __shared__ __align__(128) char sm[];
    const uint32_t smb = smem_u32(sm);
    const int m0 = blockIdx.y * 128;
    const int n0 = blockIdx.x * 128;
    const int tid = threadIdx.x;

    float acc[4][4][4];
    #pragma unroll
    for (int i = 0; i < 4; i++)
        #pragma unroll
        for (int j = 0; j < 4; j++)
            #pragma unroll
            for (int e = 0; e < 4; e++) acc[i][j][e] = 0.0f;

    g5_mainloop(smb, A, W, m0, n0, tid, acc);

    const int lane = tid & 31;
    const int wid  = tid >> 5;
    #pragma unroll
    for (int mt = 0; mt < 4; mt++) {
        const int row = m0 + (wid >> 2) * 64 + mt * 16 + (lane >> 2);
        #pragma unroll
        for (int nt = 0; nt < 4; nt++) {
            const int col = n0 + (wid & 3) * 32 + nt * 8 + (lane & 3) * 2;
            *(float2*)&C[(size_t)row * DMODEL + col] =
                make_float2(acc[mt][nt][0], acc[mt][nt][1]);
            *(float2*)&C[(size_t)(row + 8) * DMODEL + col] =
                make_float2(acc[mt][nt][2], acc[mt][nt][3]);
        }
    }
}

// ---------------------------------------------------------------------------
// Flash attention, fp16 HMMA, double-buffered KV, log2-domain softmax.
// BQ=64, BKV=64, 4 warps/CTA, 2 CTAs/SM.
// NEW: K/V fragment loads hoisted ahead of their MMA groups (R9 pattern).
// ---------------------------------------------------------------------------
#define FB_ROWB 272
#define FSTG    (2 * 64 * FB_ROWB)          // 34816 per stage (K + V)
#define FB_Q    (2 * FSTG)                  // 69632
#define FB_MSK  (FB_Q + 64 * FB_ROWB)       // 87040 (two 256 B slots)
#define FB_SMEM (FB_MSK + 512)              // 87552 -> 2 CTAs/SM

__device__ __forceinline__ void fl_loadkv64(
    uint32_t smb, int stg, const __half* __restrict__ kh,
    const __half* __restrict__ vh, const int* __restrict__ amask,
    int b, int h, int kt, int tid)
{
    const uint32_t base = smb + stg * FSTG;
    const size_t krow0 = (size_t)b * SEQ + (size_t)kt * 64;
    #pragma unroll
    for (int i = 0; i < 8; i++) {
        int idx = i * 128 + tid;
        int r = idx >> 4;
        int c = (idx & 15) * 16;
        size_t go = ((krow0 + r) * DMODEL + h * HDIM) * 2 + c;
        cp16(base + r * FB_ROWB + c, (const char*)kh + go);
        cp16(base + 64 * FB_ROWB + r * FB_ROWB + c, (const char*)vh + go);
    }
    if (tid < 16)
        cp16(smb + FB_MSK + stg * 256 + tid * 16,
             (const char*)(amask + b * SEQ + kt * 64) + tid * 16);
}

__global__ void __launch_bounds__(128, 2) flash_f16(
    const __half* __restrict__ qh, const __half* __restrict__ kh,
    const __half* __restrict__ vh, const int* __restrict__ amask,
    __half* __restrict__ chi)
{
    extern __shared__ __align__(128) char sm[];
    const uint32_t smb = smem_u32(sm);

    const int b  = blockIdx.z;
    const int h  = blockIdx.y;
    const int qt = (int)gridDim.x - 1 - (int)blockIdx.x;   // heavy tiles first
    const int tid = threadIdx.x;
    const int wid = tid >> 5;
    const int lane = tid & 31;

    const size_t qrow0 = (size_t)b * SEQ + (size_t)qt * 64;

    #pragma unroll
    for (int i = 0; i < 8; i++) {
        int idx = i * 128 + tid;
        int r = idx >> 4;
        int c = (idx & 15) * 16;
        size_t go = ((qrow0 + r) * DMODEL + h * HDIM) * 2 + c;
        cp16(smb + FB_Q + r * FB_ROWB + c, (const char*)qh + go);
    }
    fl_loadkv64(smb, 0, kh, vh, amask, b, h, 0, tid);
    CP_COMMIT;

    float o[16][4];
    #pragma unroll
    for (int nt = 0; nt < 16; nt++)
        #pragma unroll
        for (int e = 0; e < 4; e++) o[nt][e] = 0.0f;
    float mA = -1e30f, mB = -1e30f, lA = 0.0f, lB = 0.0f;
    uint32_t qf[8][4];

    const int rA = lane >> 2;
    const int growA = qt * 64 + wid * 16 + rA;
    const int growB = growA + 8;
    const uint32_t qbase = smb + FB_Q + (wid * 16 + (lane & 15)) * FB_ROWB +
                           ((lane >> 4) & 1) * 16;
    const uint32_t krel = ((lane & 7) + ((lane >> 4) << 3)) * FB_ROWB +
                          ((lane >> 3) & 1) * 16;
    const uint32_t vrel = 64 * FB_ROWB +
                          ((lane & 7) + ((lane >> 3) & 1) * 8) * FB_ROWB +
                          (lane >> 4) * 16;

    for (int kt = 0; kt <= qt; kt++) {
        CP_WAIT0;            // stage kt&1 resident
        __syncthreads();     // all warps done with stage (kt+1)&1 (iter kt-1)
        if (kt == 0) {
            #pragma unroll
            for (int kk = 0; kk < 8; kk++) ldsm4(qf[kk], qbase + kk * 32);
        }
        if (kt < qt)
            fl_loadkv64(smb, (kt + 1) & 1, kh, vh, amask, b, h, kt + 1, tid);
        CP_COMMIT;           // prefetch in flight UNDER this tile's compute

        const int stg = kt & 1;
        const uint32_t kvb = smb + stg * FSTG;
        const int* Ms = (const int*)(sm + FB_MSK + stg * 256);

        // ---- S = Qs K^T  (log2-domain scores); K fragments hoisted ----
        float s[8][4];
        #pragma unroll
        for (int nt = 0; nt < 8; nt++)
            #pragma unroll
            for (int e = 0; e < 4; e++) s[nt][e] = 0.0f;

        #pragma unroll
        for (int kk = 0; kk < 8; kk++) {
            uint32_t kf[4][4];
            #pragma unroll
            for (int g = 0; g < 4; g++)
                ldsm4(kf[g], kvb + krel + g * 16 * FB_ROWB + kk * 32);
            #pragma unroll
            for (int g = 0; g < 4; g++) {
                mma_f16(s[2 * g], qf[kk], kf[g]);
                mma_f16(s[2 * g + 1], qf[kk], kf[g] + 2);
            }
        }

        // ---- mask (warp-uniform fast path) + row max ----
        int mybit = (Ms[lane] != 0) & (Ms[lane + 32] != 0);
        bool allones = (__ballot_sync(0xffffffffu, mybit) == 0xffffffffu);
        float tmaxA = -1e30f, tmaxB = -1e30f;
        if (allones && (kt * 64 + 63 <= qt * 64 + wid * 16)) {
            #pragma unroll
            for (int nt = 0; nt < 8; nt++) {
                tmaxA = fmaxf(tmaxA, fmaxf(s[nt][0], s[nt][1]));
                tmaxB = fmaxf(tmaxB, fmaxf(s[nt][2], s[nt][3]));
            }
        } else {
            #pragma unroll
            for (int nt = 0; nt < 8; nt++) {
                int lc = nt * 8 + (lane & 3) * 2;
                int gc = kt * 64 + lc;
                int mk0 = Ms[lc], mk1 = Ms[lc + 1];
                float v0 = s[nt][0]; if (gc > growA || !mk0) v0 = -10000.0f;
                float v1 = s[nt][1]; if (gc + 1 > growA || !mk1) v1 = -10000.0f;
                float v2 = s[nt][2]; if (gc > growB || !mk0) v2 = -10000.0f;
                float v3 = s[nt][3]; if (gc + 1 > growB || !mk1) v3 = -10000.0f;
                s[nt][0] = v0; s[nt][1] = v1; s[nt][2] = v2; s[nt][3] = v3;
                tmaxA = fmaxf(tmaxA, fmaxf(v0, v1));
                tmaxB = fmaxf(tmaxB, fmaxf(v2, v3));
            }
        }
        tmaxA = fmaxf(tmaxA, __shfl_xor_sync(0xffffffffu, tmaxA, 1));
        tmaxA = fmaxf(tmaxA, __shfl_xor_sync(0xffffffffu, tmaxA, 2));
        tmaxB = fmaxf(tmaxB, __shfl_xor_sync(0xffffffffu, tmaxB, 1));
        tmaxB = fmaxf(tmaxB, __shfl_xor_sync(0xffffffffu, tmaxB, 2));

        float mAn = fmaxf(mA, tmaxA), mBn = fmaxf(mB, tmaxB);
        float aAl = ex2f(mA - mAn), aBl = ex2f(mB - mBn);

        // ---- P = exp2(S - m) -> fp16 fragments ----
        uint32_t phi[8][2];
        float sumA = 0.0f, sumB = 0.0f;
        #pragma unroll
        for (int nt = 0; nt < 8; nt++) {
            float p0 = ex2f(s[nt][0] - mAn), p1 = ex2f(s[nt][1] - mAn);
            float p2 = ex2f(s[nt][2] - mBn), p3 = ex2f(s[nt][3] - mBn);
            sumA += p0 + p1; sumB += p2 + p3;
            phi[nt][0] = pack_h2(p0, p1);
            phi[nt][1] = pack_h2(p2, p3);
        }
        sumA += __shfl_xor_sync(0xffffffffu, sumA, 1);
        sumA += __shfl_xor_sync(0xffffffffu, sumA, 2);
        sumB += __shfl_xor_sync(0xffffffffu, sumB, 1);
        sumB += __shfl_xor_sync(0xffffffffu, sumB, 2);
        lA = lA * aAl + sumA;
        lB = lB * aBl + sumB;
        mA = mAn; mB = mBn;

        // ---- O rescale (skip when no row max moved in this warp) ----
        if (__ballot_sync(0xffffffffu,
                          (aAl == 1.0f) && (aBl == 1.0f)) != 0xffffffffu) {
            #pragma unroll
            for (int nt = 0; nt < 16; nt++) {
                o[nt][0] *= aAl; o[nt][1] *= aAl;
                o[nt][2] *= aBl; o[nt][3] *= aBl;
            }
        }

        // ---- O += P V  (V fragments hoisted in pairs) ----
        #pragma unroll
        for (int t = 0; t < 4; t++) {
            uint32_t ah[4] = {phi[2 * t][0], phi[2 * t][1],
                              phi[2 * t + 1][0], phi[2 * t + 1][1]};
            #pragma unroll
            for (int gp = 0; gp < 4; gp++) {
                uint32_t vf0[4], vf1[4];
                uint32_t vaddr = kvb + vrel + t * 16 * FB_ROWB + gp * 64;
                ldsm4t(vf0, vaddr);
                ldsm4t(vf1, vaddr + 32);
                mma_f16(o[4 * gp], ah, vf0);
                mma_f16(o[4 * gp + 1], ah, vf0 + 2);
                mma_f16(o[4 * gp + 2], ah, vf1);
                mma_f16(o[4 * gp + 3], ah, vf1 + 2);
            }
        }
    }

    // ---- normalize + store context (fp16) ----
    const float invA = 1.0f / lA, invB = 1.0f / lB;
    const size_t rgA = qrow0 + wid * 16 + rA;
    const size_t rgB = rgA + 8;
    #pragma unroll
    for (int nt = 0; nt < 16; nt++) {
        int col = h * HDIM + nt * 8 + (lane & 3) * 2;
        *(uint32_t*)&chi[rgA * DMODEL + col] =
            pack_h2(o[nt][0] * invA, o[nt][1] * invA);
        *(uint32_t*)&chi[rgB * DMODEL + col] =
            pack_h2(o[nt][2] * invB, o[nt][3] * invB);
    }
}

// ---------------------------------------------------------------------------
// Launch: cvt7, gemm_qkv, flash, gemm_out  (4 launches)
// ---------------------------------------------------------------------------
extern "C" void kernel_launch(void* const* d_in, const int* in_sizes, int n_in,
                              void* d_out, int out_size)
{
    const float* query = (const float*)d_in[0];
    const float* key   = (const float*)d_in[1];
    const float* value = (const float*)d_in[2];
    const int*   amask = (const int*)  d_in[3];
    const float* Wq    = (const float*)d_in[4];
    const float* Wk    = (const float*)d_in[5];
    const float* Wv    = (const float*)d_in[6];
    const float* Wo    = (const float*)d_in[7];
    float* out = (float*)d_out;

    __half *xq, *xk, *xv, *wq, *wk, *wv, *wo, *qh, *kh, *vh, *ch;
    cudaGetSymbolAddress((void**)&xq, g_Xq);
    cudaGetSymbolAddress((void**)&xk, g_Xk);
    cudaGetSymbolAddress((void**)&xv, g_Xv);
    cudaGetSymbolAddress((void**)&wq, g_Wq);
    cudaGetSymbolAddress((void**)&wk, g_Wk);
    cudaGetSymbolAddress((void**)&wv, g_Wv);
    cudaGetSymbolAddress((void**)&wo, g_Wo);
    cudaGetSymbolAddress((void**)&qh, g_Qh);
    cudaGetSymbolAddress((void**)&kh, g_Kh);
    cudaGetSymbolAddress((void**)&vh, g_Vh);
    cudaGetSymbolAddress((void**)&ch, g_Ch);

    cudaFuncSetAttribute(gemm_qkv,
                         cudaFuncAttributeMaxDynamicSharedMemorySize, G5_SMEM);
    cudaFuncSetAttribute(gemm_out,
                         cudaFuncAttributeMaxDynamicSharedMemorySize, G5_SMEM);
    cudaFuncSetAttribute(flash_f16,
                         cudaFuncAttributeMaxDynamicSharedMemorySize, FB_SMEM);

    cvt7_f16<<<(3 * NA4 + 4 * NW4) / 256, 256>>>(
        query, key, value, Wq, Wk, Wv, Wo,
        xq, xk, xv, wq, wk, wv, wo);

    gemm_qkv<<<3072, 256, G5_SMEM>>>(xq, xk, xv, wq, wk, wv, qh, kh, vh);

    flash_f16<<<dim3(SEQ / 64, NHEAD, BATCH), 128, FB_SMEM>>>(
        qh, kh, vh, amask, ch);

    gemm_out<<<dim3(DMODEL / 128, MROWS / 128), 256, G5_SMEM>>>(ch, wo, out);
}

// round 17
// speedup vs baseline: 1.0350x; 1.0035x over previous
#include <cuda_runtime.h>
#include <cuda_fp16.h>
#include <cstdint>

// Problem constants
#define BATCH 4
#define SEQ   2048
#define DMODEL 2048
#define NHEAD 16
#define HDIM  128
#define MROWS (BATCH * SEQ)   // 8192

// ---------------------------------------------------------------------------
// Scratch (device globals; allocation in kernel_launch is forbidden)
// ---------------------------------------------------------------------------
__device__ __half g_Xq[(size_t)MROWS * DMODEL];
__device__ __half g_Xk[(size_t)MROWS * DMODEL];
__device__ __half g_Xv[(size_t)MROWS * DMODEL];
__device__ __half g_Wq[(size_t)DMODEL * DMODEL];
__device__ __half g_Wk[(size_t)DMODEL * DMODEL];
__device__ __half g_Wv[(size_t)DMODEL * DMODEL];
__device__ __half g_Wo[(size_t)DMODEL * DMODEL];
__device__ __half g_Qh[(size_t)MROWS * DMODEL];
__device__ __half g_Kh[(size_t)MROWS * DMODEL];
__device__ __half g_Vh[(size_t)MROWS * DMODEL];
__device__ __half g_Ch[(size_t)MROWS * DMODEL];

// ---------------------------------------------------------------------------
// PTX helpers (sm_80-level: mma.sync / ldmatrix / cp.async)
// ---------------------------------------------------------------------------
__device__ __forceinline__ uint32_t smem_u32(const void* p) {
    uint32_t a;
    asm("{ .reg .u64 t; cvta.to.shared.u64 t, %1; cvt.u32.u64 %0, t; }"
        : "=r"(a) : "l"(p));
    return a;
}
__device__ __forceinline__ void ldsm4(uint32_t* r, uint32_t addr) {
    asm volatile("ldmatrix.sync.aligned.m8n8.x4.shared.b16 {%0,%1,%2,%3}, [%4];"
                 : "=r"(r[0]), "=r"(r[1]), "=r"(r[2]), "=r"(r[3]) : "r"(addr));
}
__device__ __forceinline__ void ldsm4t(uint32_t* r, uint32_t addr) {
    asm volatile("ldmatrix.sync.aligned.m8n8.x4.trans.shared.b16 {%0,%1,%2,%3}, [%4];"
                 : "=r"(r[0]), "=r"(r[1]), "=r"(r[2]), "=r"(r[3]) : "r"(addr));
}
__device__ __forceinline__ void mma_f16(float* d, const uint32_t* a,
                                        const uint32_t* b) {
    asm volatile(
        "mma.sync.aligned.m16n8k16.row.col.f32.f16.f16.f32 "
        "{%0,%1,%2,%3}, {%4,%5,%6,%7}, {%8,%9}, {%0,%1,%2,%3};"
        : "+f"(d[0]), "+f"(d[1]), "+f"(d[2]), "+f"(d[3])
        : "r"(a[0]), "r"(a[1]), "r"(a[2]), "r"(a[3]), "r"(b[0]), "r"(b[1]));
}
// Uniform .ca (R14 proven best): co-resident CTAs share A / KV tiles via L1.
__device__ __forceinline__ void cp16(uint32_t dst, const void* src) {
    asm volatile("cp.async.ca.shared.global [%0], [%1], 16;"
                 :: "r"(dst), "l"(src) : "memory");
}
#define CP_COMMIT asm volatile("cp.async.commit_group;" ::: "memory")
#define CP_WAIT0  asm volatile("cp.async.wait_group 0;" ::: "memory")

// pack two fp32 -> half2 (first arg -> low half)
__device__ __forceinline__ uint32_t pack_h2(float lo, float hi) {
    uint32_t r;
    asm("cvt.rn.f16x2.f32 %0, %1, %2;" : "=r"(r) : "f"(hi), "f"(lo));
    return r;
}
// raw exp2 (MUFU.EX2) — softmax runs in log2 domain
__device__ __forceinline__ float ex2f(float x) {
    float r;
    asm("ex2.approx.f32 %0, %1;" : "=f"(r) : "f"(x));
    return r;
}

// 1/sqrt(128) * log2(e): folded into Q so QK^T scores are log2-domain.
#define QSCALE (0.08838834764831843f * 1.4426950408889634f)

// ---------------------------------------------------------------------------
// Fused converts (fp32 -> fp16): q,k,v,Wq,Wk,Wv,Wo in ONE launch
// ---------------------------------------------------------------------------
#define NA4 (MROWS * DMODEL / 4)     // 4194304
#define NW4 (DMODEL * DMODEL / 4)    // 1048576

__global__ void __launch_bounds__(256) cvt7_f16(
    const float* __restrict__ x0, const float* __restrict__ x1,
    const float* __restrict__ x2,
    const float* __restrict__ w0, const float* __restrict__ w1,
    const float* __restrict__ w2, const float* __restrict__ w3,
    __half* __restrict__ a0, __half* __restrict__ a1, __half* __restrict__ a2,
    __half* __restrict__ b0, __half* __restrict__ b1,
    __half* __restrict__ b2, __half* __restrict__ b3)
{
    int i = blockIdx.x * 256 + threadIdx.x;
    const float* x;
    __half* h;
    int j;
    if (i < 3 * NA4) {
        int which = i / NA4;
        j = i - which * NA4;
        x = (which == 0) ? x0 : (which == 1) ? x1 : x2;
        h = (which == 0) ? a0 : (which == 1) ? a1 : a2;
    } else {
        int k = i - 3 * NA4;
        int which = k / NW4;
        j = k - which * NW4;
        x = (which == 0) ? w0 : (which == 1) ? w1 : (which == 2) ? w2 : w3;
        h = (which == 0) ? b0 : (which == 1) ? b1 : (which == 2) ? b2 : b3;
    }
    float4 v = ((const float4*)x)[j];
    ((uint2*)h)[j] = make_uint2(pack_h2(v.x, v.y), pack_h2(v.z, v.w));
}

// ---------------------------------------------------------------------------
// fp16 single-term GEMM (R14 config):  C = A @ W^T
// CTA 128x128, BK=64, 8 warps (2x4, warp 64x32), 2-stage cp.async double
// buffer, 2 CTAs/SM. Rows padded to 144 B. Fragment loads hoisted per k16.
// ---------------------------------------------------------------------------
#define G5_ROWB  144
#define G5_TILE  (128 * G5_ROWB)     // 18432
#define G5_STAGE (2 * G5_TILE)       // 36864 (A, W)
#define G5_SMEM  (2 * G5_STAGE)      // 73728 -> 2 CTAs/SM

__device__ __forceinline__ void g5_load(
    uint32_t smb, int stage, const __half* __restrict__ A,
    const __half* __restrict__ W, int m0, int n0, int k0, int tid)
{
    const __half* srcs[2] = {A + (size_t)m0 * DMODEL + k0,
                             W + (size_t)n0 * DMODEL + k0};
    #pragma unroll
    for (int t = 0; t < 2; t++) {
        #pragma unroll
        for (int i = 0; i < 4; i++) {
            int v = i * 256 + tid;          // 0..1023 16B chunks
            int r = v >> 3;                 // 0..127
            int c = (v & 7) * 16;           // 0..112
            cp16(smb + stage * G5_STAGE + t * G5_TILE + r * G5_ROWB + c,
                 (const char*)srcs[t] + (size_t)r * DMODEL * 2 + c);
        }
    }
}

__device__ __forceinline__ void g5_mainloop(
    uint32_t smb, const __half* __restrict__ A, const __half* __restrict__ W,
    int m0, int n0, int tid, float acc[4][4][4])
{
    const int lane = tid & 31;
    const int wid  = tid >> 5;
    const int wm = wid >> 2;
    const int wn = wid & 3;
    const int a_row = wm * 64 + (lane & 15);
    const int a_cb  = ((lane >> 4) & 1) * 16;
    const int b_row = wn * 32 + (lane & 7) + ((lane >> 4) << 3);
    const int b_cb  = ((lane >> 3) & 1) * 16;

    const int nchunks = DMODEL / 64;   // 32
    g5_load(smb, 0, A, W, m0, n0, 0, tid);
    CP_COMMIT;

    for (int c = 0; c < nchunks; c++) {
        CP_WAIT0;
        __syncthreads();
        if (c + 1 < nchunks) {
            g5_load(smb, (c + 1) & 1, A, W, m0, n0, (c + 1) * 64, tid);
            CP_COMMIT;
        }

        const uint32_t st = smb + (c & 1) * G5_STAGE;
        #pragma unroll
        for (int kk = 0; kk < 4; kk++) {
            const int kb = kk * 32;
            uint32_t bh[4][2];
            #pragma unroll
            for (int nt2 = 0; nt2 < 2; nt2++) {
                uint32_t r4[4];
                ldsm4(r4, st + G5_TILE +
                          (b_row + nt2 * 16) * G5_ROWB + kb + b_cb);
                bh[nt2 * 2][0] = r4[0]; bh[nt2 * 2][1] = r4[1];
                bh[nt2 * 2 + 1][0] = r4[2]; bh[nt2 * 2 + 1][1] = r4[3];
            }
            uint32_t ah[4][4];
            #pragma unroll
            for (int mt = 0; mt < 4; mt++)
                ldsm4(ah[mt], st + (a_row + mt * 16) * G5_ROWB + kb + a_cb);
            #pragma unroll
            for (int mt = 0; mt < 4; mt++)
                #pragma unroll
                for (int nt = 0; nt < 4; nt++)
                    mma_f16(acc[mt][nt], ah[mt], bh[nt]);
        }
    }
}

// Fused Q/K/V projection GEMM: 3072 tiles. Q gets QSCALE (incl log2e) folded.
__global__ void __launch_bounds__(256, 2) gemm_qkv(
    const __half* __restrict__ xq, const __half* __restrict__ xk,
    const __half* __restrict__ xv,
    const __half* __restrict__ wq, const __half* __restrict__ wk,
    const __half* __restrict__ wv,
    __half* __restrict__ qh, __half* __restrict__ kh, __half* __restrict__ vh)
{
    extern __shared__ __align__(128) char sm[];
    const uint32_t smb = smem_u32(sm);
    const int t = blockIdx.x;
    const int which = t >> 10;
    const int idx = t & 1023;
    const int m0 = (idx >> 4) * 128;
    const int n0 = (idx & 15) * 128;
    const int tid = threadIdx.x;

    const __half* A = (which == 0) ? xq : (which == 1) ? xk : xv;
    const __half* W = (which == 0) ? wq : (which == 1) ? wk : wv;
    __half* Oh = (which == 0) ? qh : (which == 1) ? kh : vh;

    float acc[4][4][4];
    #pragma unroll
    for (int i = 0; i < 4; i++)
        #pragma unroll
        for (int j = 0; j < 4; j++)
            #pragma unroll
            for (int e = 0; e < 4; e++) acc[i][j][e] = 0.0f;

    g5_mainloop(smb, A, W, m0, n0, tid, acc);

    const int lane = tid & 31;
    const int wid  = tid >> 5;
    const float sc = (which == 0) ? QSCALE : 1.0f;
    #pragma unroll
    for (int mt = 0; mt < 4; mt++) {
        const int row = m0 + (wid >> 2) * 64 + mt * 16 + (lane >> 2);
        #pragma unroll
        for (int nt = 0; nt < 4; nt++) {
            const int col = n0 + (wid & 3) * 32 + nt * 8 + (lane & 3) * 2;
            *(uint32_t*)&Oh[(size_t)row * DMODEL + col] =
                pack_h2(acc[mt][nt][0] * sc, acc[mt][nt][1] * sc);
            *(uint32_t*)&Oh[(size_t)(row + 8) * DMODEL + col] =
                pack_h2(acc[mt][nt][2] * sc, acc[mt][nt][3] * sc);
        }
    }
}

// Output projection GEMM: fp32 result to d_out via streaming stores
// (__stcs: output is write-once/never-read -> keep ch & wo resident in L2).
__global__ void __launch_bounds__(256, 2) gemm_out(
    const __half* __restrict__ A, const __half* __restrict__ W,
    float* __restrict__ C)
{
    extern __shared__ __align__(128) char sm[];
    const uint32_t smb = smem_u32(sm);
    const int m0 = blockIdx.y * 128;
    const int n0 = blockIdx.x * 128;
    const int tid = threadIdx.x;

    float acc[4][4][4];
    #pragma unroll
    for (int i = 0; i < 4; i++)
        #pragma unroll
        for (int j = 0; j < 4; j++)
            #pragma unroll
            for (int e = 0; e < 4; e++) acc[i][j][e] = 0.0f;

    g5_mainloop(smb, A, W, m0, n0, tid, acc);

    const int lane = tid & 31;
    const int wid  = tid >> 5;
    #pragma unroll
    for (int mt = 0; mt < 4; mt++) {
        const int row = m0 + (wid >> 2) * 64 + mt * 16 + (lane >> 2);
        #pragma unroll
        for (int nt = 0; nt < 4; nt++) {
            const int col = n0 + (wid & 3) * 32 + nt * 8 + (lane & 3) * 2;
            __stcs((float2*)&C[(size_t)row * DMODEL + col],
                   make_float2(acc[mt][nt][0], acc[mt][nt][1]));
            __stcs((float2*)&C[(size_t)(row + 8) * DMODEL + col],
                   make_float2(acc[mt][nt][2], acc[mt][nt][3]));
        }
    }
}

// ---------------------------------------------------------------------------
// Flash attention (R14 config), fp16 HMMA, double-buffered KV,
// log2-domain softmax. BQ=64, BKV=64, 4 warps/CTA, 2 CTAs/SM.
// ---------------------------------------------------------------------------
#define FB_ROWB 272
#define FSTG    (2 * 64 * FB_ROWB)          // 34816 per stage (K + V)
#define FB_Q    (2 * FSTG)                  // 69632
#define FB_MSK  (FB_Q + 64 * FB_ROWB)       // 87040 (two 256 B slots)
#define FB_SMEM (FB_MSK + 512)              // 87552 -> 2 CTAs/SM

__device__ __forceinline__ void fl_loadkv64(
    uint32_t smb, int stg, const __half* __restrict__ kh,
    const __half* __restrict__ vh, const int* __restrict__ amask,
    int b, int h, int kt, int tid)
{
    const uint32_t base = smb + stg * FSTG;
    const size_t krow0 = (size_t)b * SEQ + (size_t)kt * 64;
    #pragma unroll
    for (int i = 0; i < 8; i++) {
        int idx = i * 128 + tid;
        int r = idx >> 4;
        int c = (idx & 15) * 16;
        size_t go = ((krow0 + r) * DMODEL + h * HDIM) * 2 + c;
        cp16(base + r * FB_ROWB + c, (const char*)kh + go);
        cp16(base + 64 * FB_ROWB + r * FB_ROWB + c, (const char*)vh + go);
    }
    if (tid < 16)
        cp16(smb + FB_MSK + stg * 256 + tid * 16,
             (const char*)(amask + b * SEQ + kt * 64) + tid * 16);
}

__global__ void __launch_bounds__(128, 2) flash_f16(
    const __half* __restrict__ qh, const __half* __restrict__ kh,
    const __half* __restrict__ vh, const int* __restrict__ amask,
    __half* __restrict__ chi)
{
    extern __shared__ __align__(128) char sm[];
    const uint32_t smb = smem_u32(sm);

    const int b  = blockIdx.z;
    const int h  = blockIdx.y;
    const int qt = (int)gridDim.x - 1 - (int)blockIdx.x;   // heavy tiles first
    const int tid = threadIdx.x;
    const int wid = tid >> 5;
    const int lane = tid & 31;

    const size_t qrow0 = (size_t)b * SEQ + (size_t)qt * 64;

    #pragma unroll
    for (int i = 0; i < 8; i++) {
        int idx = i * 128 + tid;
        int r = idx >> 4;
        int c = (idx & 15) * 16;
        size_t go = ((qrow0 + r) * DMODEL + h * HDIM) * 2 + c;
        cp16(smb + FB_Q + r * FB_ROWB + c, (const char*)qh + go);
    }
    fl_loadkv64(smb, 0, kh, vh, amask, b, h, 0, tid);
    CP_COMMIT;

    float o[16][4];
    #pragma unroll
    for (int nt = 0; nt < 16; nt++)
        #pragma unroll
        for (int e = 0; e < 4; e++) o[nt][e] = 0.0f;
    float mA = -1e30f, mB = -1e30f, lA = 0.0f, lB = 0.0f;
    uint32_t qf[8][4];

    const int rA = lane >> 2;
    const int growA = qt * 64 + wid * 16 + rA;
    const int growB = growA + 8;
    const uint32_t qbase = smb + FB_Q + (wid * 16 + (lane & 15)) * FB_ROWB +
                           ((lane >> 4) & 1) * 16;
    const uint32_t krel = ((lane & 7) + ((lane >> 4) << 3)) * FB_ROWB +
                          ((lane >> 3) & 1) * 16;
    const uint32_t vrel = 64 * FB_ROWB +
                          ((lane & 7) + ((lane >> 3) & 1) * 8) * FB_ROWB +
                          (lane >> 4) * 16;

    for (int kt = 0; kt <= qt; kt++) {
        CP_WAIT0;            // stage kt&1 resident
        __syncthreads();     // all warps done with stage (kt+1)&1 (iter kt-1)
        if (kt == 0) {
            #pragma unroll
            for (int kk = 0; kk < 8; kk++) ldsm4(qf[kk], qbase + kk * 32);
        }
        if (kt < qt)
            fl_loadkv64(smb, (kt + 1) & 1, kh, vh, amask, b, h, kt + 1, tid);
        CP_COMMIT;           // prefetch in flight UNDER this tile's compute

        const int stg = kt & 1;
        const uint32_t kvb = smb + stg * FSTG;
        const int* Ms = (const int*)(sm + FB_MSK + stg * 256);

        // ---- S = Qs K^T  (log2-domain scores) ----
        float s[8][4];
        #pragma unroll
        for (int nt = 0; nt < 8; nt++)
            #pragma unroll
            for (int e = 0; e < 4; e++) s[nt][e] = 0.0f;

        #pragma unroll
        for (int kk = 0; kk < 8; kk++) {
            #pragma unroll
            for (int g = 0; g < 4; g++) {
                uint32_t kf[4];
                ldsm4(kf, kvb + krel + g * 16 * FB_ROWB + kk * 32);
                mma_f16(s[2 * g], qf[kk], kf);
                mma_f16(s[2 * g + 1], qf[kk], kf + 2);
            }
        }

        // ---- mask (warp-uniform fast path) + row max ----
        int mybit = (Ms[lane] != 0) & (Ms[lane + 32] != 0);
        bool allones = (__ballot_sync(0xffffffffu, mybit) == 0xffffffffu);
        float tmaxA = -1e30f, tmaxB = -1e30f;
        if (allones && (kt * 64 + 63 <= qt * 64 + wid * 16)) {
            #pragma unroll
            for (int nt = 0; nt < 8; nt++) {
                tmaxA = fmaxf(tmaxA, fmaxf(s[nt][0], s[nt][1]));
                tmaxB = fmaxf(tmaxB, fmaxf(s[nt][2], s[nt][3]));
            }
        } else {
            #pragma unroll
            for (int nt = 0; nt < 8; nt++) {
                int lc = nt * 8 + (lane & 3) * 2;
                int gc = kt * 64 + lc;
                int mk0 = Ms[lc], mk1 = Ms[lc + 1];
                float v0 = s[nt][0]; if (gc > growA || !mk0) v0 = -10000.0f;
                float v1 = s[nt][1]; if (gc + 1 > growA || !mk1) v1 = -10000.0f;
                float v2 = s[nt][2]; if (gc > growB || !mk0) v2 = -10000.0f;
                float v3 = s[nt][3]; if (gc + 1 > growB || !mk1) v3 = -10000.0f;
                s[nt][0] = v0; s[nt][1] = v1; s[nt][2] = v2; s[nt][3] = v3;
                tmaxA = fmaxf(tmaxA, fmaxf(v0, v1));
                tmaxB = fmaxf(tmaxB, fmaxf(v2, v3));
            }
        }
        tmaxA = fmaxf(tmaxA, __shfl_xor_sync(0xffffffffu, tmaxA, 1));
        tmaxA = fmaxf(tmaxA, __shfl_xor_sync(0xffffffffu, tmaxA, 2));
        tmaxB = fmaxf(tmaxB, __shfl_xor_sync(0xffffffffu, tmaxB, 1));
        tmaxB = fmaxf(tmaxB, __shfl_xor_sync(0xffffffffu, tmaxB, 2));

        float mAn = fmaxf(mA, tmaxA), mBn = fmaxf(mB, tmaxB);
        float aAl = ex2f(mA - mAn), aBl = ex2f(mB - mBn);

        // ---- P = exp2(S - m) -> fp16 fragments ----
        uint32_t phi[8][2];
        float sumA = 0.0f, sumB = 0.0f;
        #pragma unroll
        for (int nt = 0; nt < 8; nt++) {
            float p0 = ex2f(s[nt][0] - mAn), p1 = ex2f(s[nt][1] - mAn);
            float p2 = ex2f(s[nt][2] - mBn), p3 = ex2f(s[nt][3] - mBn);
            sumA += p0 + p1; sumB += p2 + p3;
            phi[nt][0] = pack_h2(p0, p1);
            phi[nt][1] = pack_h2(p2, p3);
        }
        sumA += __shfl_xor_sync(0xffffffffu, sumA, 1);
        sumA += __shfl_xor_sync(0xffffffffu, sumA, 2);
        sumB += __shfl_xor_sync(0xffffffffu, sumB, 1);
        sumB += __shfl_xor_sync(0xffffffffu, sumB, 2);
        lA = lA * aAl + sumA;
        lB = lB * aBl + sumB;
        mA = mAn; mB = mBn;

        // ---- O rescale (skip when no row max moved in this warp) ----
        if (__ballot_sync(0xffffffffu,
                          (aAl == 1.0f) && (aBl == 1.0f)) != 0xffffffffu) {
            #pragma unroll
            for (int nt = 0; nt < 16; nt++) {
                o[nt][0] *= aAl; o[nt][1] *= aAl;
                o[nt][2] *= aBl; o[nt][3] *= aBl;
            }
        }

        // ---- O += P V ----
        #pragma unroll
        for (int t = 0; t < 4; t++) {
            uint32_t ah[4] = {phi[2 * t][0], phi[2 * t][1],
                              phi[2 * t + 1][0], phi[2 * t + 1][1]};
            #pragma unroll
            for (int g = 0; g < 8; g++) {
                uint32_t vf[4];
                ldsm4t(vf, kvb + vrel + t * 16 * FB_ROWB + g * 32);
                mma_f16(o[2 * g], ah, vf);
                mma_f16(o[2 * g + 1], ah, vf + 2);
            }
        }
    }

    // ---- normalize + store context (fp16) ----
    const float invA = 1.0f / lA, invB = 1.0f / lB;
    const size_t rgA = qrow0 + wid * 16 + rA;
    const size_t rgB = rgA + 8;
    #pragma unroll
    for (int nt = 0; nt < 16; nt++) {
        int col = h * HDIM + nt * 8 + (lane & 3) * 2;
        *(uint32_t*)&chi[rgA * DMODEL + col] =
            pack_h2(o[nt][0] * invA, o[nt][1] * invA);
        *(uint32_t*)&chi[rgB * DMODEL + col] =
            pack_h2(o[nt][2] * invB, o[nt][3] * invB);
    }
}

// ---------------------------------------------------------------------------
// Launch: cvt7, gemm_qkv, flash, gemm_out  (4 launches)
// ---------------------------------------------------------------------------
extern "C" void kernel_launch(void* const* d_in, const int* in_sizes, int n_in,
                              void* d_out, int out_size)
{
    const float* query = (const float*)d_in[0];
    const float* key   = (const float*)d_in[1];
    const float* value = (const float*)d_in[2];
    const int*   amask = (const int*)  d_in[3];
    const float* Wq    = (const float*)d_in[4];
    const float* Wk    = (const float*)d_in[5];
    const float* Wv    = (const float*)d_in[6];
    const float* Wo    = (const float*)d_in[7];
    float* out = (float*)d_out;

    __half *xq, *xk, *xv, *wq, *wk, *wv, *wo, *qh, *kh, *vh, *ch;
    cudaGetSymbolAddress((void**)&xq, g_Xq);
    cudaGetSymbolAddress((void**)&xk, g_Xk);
    cudaGetSymbolAddress((void**)&xv, g_Xv);
    cudaGetSymbolAddress((void**)&wq, g_Wq);
    cudaGetSymbolAddress((void**)&wk, g_Wk);
    cudaGetSymbolAddress((void**)&wv, g_Wv);
    cudaGetSymbolAddress((void**)&wo, g_Wo);
    cudaGetSymbolAddress((void**)&qh, g_Qh);
    cudaGetSymbolAddress((void**)&kh, g_Kh);
    cudaGetSymbolAddress((void**)&vh, g_Vh);
    cudaGetSymbolAddress((void**)&ch, g_Ch);

    cudaFuncSetAttribute(gemm_qkv,
                         cudaFuncAttributeMaxDynamicSharedMemorySize, G5_SMEM);
    cudaFuncSetAttribute(gemm_out,
                         cudaFuncAttributeMaxDynamicSharedMemorySize, G5_SMEM);
    cudaFuncSetAttribute(flash_f16,
                         cudaFuncAttributeMaxDynamicSharedMemorySize, FB_SMEM);

    cvt7_f16<<<(3 * NA4 + 4 * NW4) / 256, 256>>>(
        query, key, value, Wq, Wk, Wv, Wo,
        xq, xk, xv, wq, wk, wv, wo);

    gemm_qkv<<<3072, 256, G5_SMEM>>>(xq, xk, xv, wq, wk, wv, qh, kh, vh);

    flash_f16<<<dim3(SEQ / 64, NHEAD, BATCH), 128, FB_SMEM>>>(
        qh, kh, vh, amask, ch);

    gemm_out<<<dim3(DMODEL / 128, MROWS / 128), 256, G5_SMEM>>>(ch, wo, out);
}